// round 4
// baseline (speedup 1.0000x reference)
#include <cuda_runtime.h>
#include <cuda_bf16.h>
#include <stdint.h>

#define KNS 100000
#define KNT 50000
#define KE  600000
#define KD  128
#define BN_EPS 1e-5f
#define SROW 136       // smem row stride in bf16 elems (128 + 8 pad)
#define NBLK_G 782     // ceil(KNT/64)
#define NBLK_B 98      // builder blocks (resident)

// ---------------- scratch (static device memory; no allocations) ----------------
__device__ float g_y1[KNT * KD];
__device__ int   g_counts[KNT];
__device__ int   g_offsets[KNT + 1];
__device__ int   g_cursor[KNT];
__device__ int   g_srcs[KE];
__device__ float g_psum[NBLK_G * KD];
__device__ float g_psq[NBLK_G * KD];
__device__ float g_scale[2 * KD];
__device__ float g_shift[2 * KD];
__device__ int   g_bsum[128];
__device__ unsigned g_bar;
__device__ __nv_bfloat16 g_Wh[2 * KD * KD];
__device__ __nv_bfloat16 g_Wl[2 * KD * KD];

// ---------------- device-wide barrier (all NBLK_B blocks resident) ----------------
__device__ __forceinline__ void gridbar(unsigned target) {
  __syncthreads();
  if (threadIdx.x == 0) {
    __threadfence();
    atomicAdd(&g_bar, 1u);
    while (*((volatile unsigned*)&g_bar) < target) {}
  }
  __syncthreads();
}

// ---------------- precompute hi/lo bf16 split of weights; reset barrier ----------
__global__ void splitw_kernel(const float* __restrict__ W1,
                              const float* __restrict__ W2) {
  int i = blockIdx.x * 256 + threadIdx.x;  // 0..8191, 4 elems each
  if (i == 0) g_bar = 0;
  if (i >= 8192) return;
  const float* W = (i < 4096) ? W1 : W2;
  int local = (i < 4096) ? i : (i - 4096);
  float4 v = *reinterpret_cast<const float4*>(W + local * 4);
  float arr[4] = {v.x, v.y, v.z, v.w};
  int o = i * 4;
#pragma unroll
  for (int j = 0; j < 4; j++) {
    __nv_bfloat16 h = __float2bfloat16_rn(arr[j]);
    g_Wh[o + j] = h;
    g_Wl[o + j] = __float2bfloat16_rn(arr[j] - __bfloat162float(h));
  }
}

__device__ __forceinline__ int warp_incl_scan(int x, int lane) {
#pragma unroll
  for (int o = 1; o < 32; o <<= 1) {
    int y = __shfl_up_sync(0xffffffffu, x, o);
    if (lane >= o) x += y;
  }
  return x;
}

// ---------------- builder: zero + histogram + exclusive scan in ONE kernel --------
__global__ void build_kernel(const int* __restrict__ dst) {
  __shared__ int ws[16];
  __shared__ int sbase;
  int t = threadIdx.x, b = blockIdx.x;
  int i = b * 512 + t;
  int lane = t & 31, w = t >> 5;

  // phase 0: zero counts
  if (i < KNT) g_counts[i] = 0;
  gridbar(NBLK_B);

  // phase 1: vectorized histogram (indices are int32: JAX x64 disabled)
  const int4* dst4 = reinterpret_cast<const int4*>(dst);
  for (int e = i; e < KE / 4; e += NBLK_B * 512) {
    int4 d = dst4[e];
    atomicAdd(&g_counts[d.x], 1);
    atomicAdd(&g_counts[d.y], 1);
    atomicAdd(&g_counts[d.z], 1);
    atomicAdd(&g_counts[d.w], 1);
  }
  gridbar(2 * NBLK_B);

  // phase 2: exclusive scan
  int v = (i < KNT) ? __ldcg(&g_counts[i]) : 0;
  int x = warp_incl_scan(v, lane);
  if (lane == 31) ws[w] = x;
  __syncthreads();
  if (t < 16) {
    int y = ws[t];
#pragma unroll
    for (int o = 1; o < 16; o <<= 1) {
      int z = __shfl_up_sync(0xffffu, y, o);
      if (t >= o) y += z;
    }
    ws[t] = y;
  }
  __syncthreads();
  int incl = x + (w > 0 ? ws[w - 1] : 0);
  int ex = incl - v;
  if (t == 511) g_bsum[b] = incl;
  gridbar(3 * NBLK_B);  // includes fence + syncthreads (ws safe to reuse after)

  int contrib = (t < b) ? __ldcg(&g_bsum[t]) : 0;  // b <= 97 < 512
#pragma unroll
  for (int o = 16; o; o >>= 1) contrib += __shfl_down_sync(0xffffffffu, contrib, o);
  if (lane == 0) ws[w] = contrib;
  __syncthreads();
  if (t == 0) {
    int s = 0;
#pragma unroll
    for (int j = 0; j < 16; j++) s += ws[j];
    sbase = s;
  }
  __syncthreads();
  int off = ex + sbase;
  if (i < KNT) {
    g_offsets[i] = off;
    g_cursor[i] = off;
  }
  if (b == 0 && t == 0) g_offsets[KNT] = KE;
}

// ---------------- scatter src ids into CSR order (vectorized) ----------------------
__global__ void scatter_kernel(const int* __restrict__ src,
                               const int* __restrict__ dst) {
  int i = blockIdx.x * blockDim.x + threadIdx.x;
  if (i >= KE / 4) return;
  int4 s = reinterpret_cast<const int4*>(src)[i];
  int4 d = reinterpret_cast<const int4*>(dst)[i];
  g_srcs[atomicAdd(&g_cursor[d.x], 1)] = s.x;
  g_srcs[atomicAdd(&g_cursor[d.y], 1)] = s.y;
  g_srcs[atomicAdd(&g_cursor[d.z], 1)] = s.z;
  g_srcs[atomicAdd(&g_cursor[d.w], 1)] = s.w;
}

// ---------------- GEMM (tensor core, bf16 hi/lo split) + fused BN stats -----------
// LAYER==1: A = aggregate(x_s, x_t) computed in-kernel,  out = g_y1
// LAYER==2: A = relu(bn1(g_y1)),                         out = out_param (d_out)
__device__ __forceinline__ void mma_bf16(float* c, const uint32_t* a,
                                         uint32_t b0, uint32_t b1) {
  asm volatile(
      "mma.sync.aligned.m16n8k16.row.col.f32.bf16.bf16.f32 "
      "{%0,%1,%2,%3}, {%4,%5,%6,%7}, {%8,%9}, {%0,%1,%2,%3};\n"
      : "+f"(c[0]), "+f"(c[1]), "+f"(c[2]), "+f"(c[3])
      : "r"(a[0]), "r"(a[1]), "r"(a[2]), "r"(a[3]), "r"(b0), "r"(b1));
}

__device__ __forceinline__ void split_bf16(float x, __nv_bfloat16& h, __nv_bfloat16& l) {
  h = __float2bfloat16_rn(x);
  l = __float2bfloat16_rn(x - __bfloat162float(h));
}

template <int LAYER>
__global__ __launch_bounds__(256, 2) void gemm_kernel(const float* __restrict__ xs,
                                                      const float* __restrict__ xt,
                                                      const float* __restrict__ eps,
                                                      const float* __restrict__ bias,
                                                      float* __restrict__ out_param) {
  extern __shared__ __nv_bfloat16 sm[];
  __nv_bfloat16* Ah = sm;
  __nv_bfloat16* Al = Ah + 64 * SROW;
  __nv_bfloat16* Wh = Al + 64 * SROW;
  __nv_bfloat16* Wl = Wh + 128 * SROW;
  float* biasS = reinterpret_cast<float*>(Wl + 128 * SROW);  // 128
  float* ssum = biasS + 128;                                  // 4*128
  float* ssq = ssum + 512;                                    // 4*128

  float* out = (LAYER == 1) ? g_y1 : out_param;
  const __nv_bfloat16* GWh = g_Wh + (LAYER - 1) * KD * KD;
  const __nv_bfloat16* GWl = g_Wl + (LAYER - 1) * KD * KD;

  int t = threadIdx.x;
  int row0 = blockIdx.x * 64;
  int w = t >> 5, lane = t & 31;

  if (t < 128) biasS[t] = bias[t];

  // stage W (precomputed bf16 hi/lo) via uint4 copies
  for (int idx = t; idx < 2048; idx += 256) {
    int r = idx >> 4;
    int c = (idx & 15) << 3;
    *reinterpret_cast<uint4*>(&Wh[r * SROW + c]) =
        *reinterpret_cast<const uint4*>(&GWh[r * 128 + c]);
    *reinterpret_cast<uint4*>(&Wl[r * SROW + c]) =
        *reinterpret_cast<const uint4*>(&GWl[r * 128 + c]);
  }

  if (LAYER == 1) {
    // fused aggregation: warp w handles tile rows w*8 .. w*8+7
    float sc = 1.0f + eps[0];
    const float4* xs4 = reinterpret_cast<const float4*>(xs);
    const float4* xt4 = reinterpret_cast<const float4*>(xt);
#pragma unroll
    for (int j = 0; j < 8; j++) {
      int tr = w * 8 + j;
      int n = row0 + tr;
      float4 a = make_float4(0.f, 0.f, 0.f, 0.f);
      if (n < KNT) {
        a = xt4[(size_t)n * 32 + lane];
        a.x *= sc; a.y *= sc; a.z *= sc; a.w *= sc;
        float4 a1 = make_float4(0.f, 0.f, 0.f, 0.f);
        float4 a2 = make_float4(0.f, 0.f, 0.f, 0.f);
        float4 a3 = make_float4(0.f, 0.f, 0.f, 0.f);
        int beg = g_offsets[n], end = g_offsets[n + 1];
        int i = beg;
        for (; i + 3 < end; i += 4) {
          int s0 = g_srcs[i], s1 = g_srcs[i + 1], s2 = g_srcs[i + 2], s3 = g_srcs[i + 3];
          float4 v0 = xs4[(size_t)s0 * 32 + lane];
          float4 v1 = xs4[(size_t)s1 * 32 + lane];
          float4 v2 = xs4[(size_t)s2 * 32 + lane];
          float4 v3 = xs4[(size_t)s3 * 32 + lane];
          a.x += v0.x;  a.y += v0.y;  a.z += v0.z;  a.w += v0.w;
          a1.x += v1.x; a1.y += v1.y; a1.z += v1.z; a1.w += v1.w;
          a2.x += v2.x; a2.y += v2.y; a2.z += v2.z; a2.w += v2.w;
          a3.x += v3.x; a3.y += v3.y; a3.z += v3.z; a3.w += v3.w;
        }
        for (; i < end; i++) {
          float4 v0 = xs4[(size_t)g_srcs[i] * 32 + lane];
          a.x += v0.x; a.y += v0.y; a.z += v0.z; a.w += v0.w;
        }
        a.x += a1.x + a2.x + a3.x;
        a.y += a1.y + a2.y + a3.y;
        a.z += a1.z + a2.z + a3.z;
        a.w += a1.w + a2.w + a3.w;
      }
      float vv[4] = {a.x, a.y, a.z, a.w};
      int c = lane << 2;
#pragma unroll
      for (int q = 0; q < 4; q++) {
        __nv_bfloat16 h, l;
        split_bf16(vv[q], h, l);
        Ah[tr * SROW + c + q] = h;
        Al[tr * SROW + c + q] = l;
      }
    }
  } else {
    // stage A = relu(bn1(g_y1))
    for (int idx = t; idx < 64 * 32; idx += 256) {
      int r = idx >> 5;
      int c = (idx & 31) << 2;
      int grow = row0 + r;
      float4 v = make_float4(0.f, 0.f, 0.f, 0.f);
      if (grow < KNT) v = *reinterpret_cast<const float4*>(g_y1 + (size_t)grow * 128 + c);
      float vv[4] = {v.x, v.y, v.z, v.w};
#pragma unroll
      for (int j = 0; j < 4; j++) {
        float x = fmaxf(fmaf(__ldg(&g_scale[c + j]), vv[j], __ldg(&g_shift[c + j])), 0.f);
        __nv_bfloat16 h, l;
        split_bf16(x, h, l);
        Ah[r * SROW + c + j] = h;
        Al[r * SROW + c + j] = l;
      }
    }
  }
  __syncthreads();

  int rq = lane >> 2;        // 0..7
  int kq = (lane & 3) << 1;  // 0,2,4,6
  int rb = (w >> 1) * 16;
  int cb = (w & 1) * 64;

  float acc[8][4];
#pragma unroll
  for (int i = 0; i < 8; i++)
#pragma unroll
    for (int j = 0; j < 4; j++) acc[i][j] = 0.f;

#pragma unroll
  for (int kk = 0; kk < 128; kk += 16) {
    uint32_t ah[4], al[4];
    const __nv_bfloat16* pa = &Ah[(rb + rq) * SROW + kk + kq];
    const __nv_bfloat16* pl = &Al[(rb + rq) * SROW + kk + kq];
    ah[0] = *reinterpret_cast<const uint32_t*>(pa);
    ah[1] = *reinterpret_cast<const uint32_t*>(pa + 8 * SROW);
    ah[2] = *reinterpret_cast<const uint32_t*>(pa + 8);
    ah[3] = *reinterpret_cast<const uint32_t*>(pa + 8 * SROW + 8);
    al[0] = *reinterpret_cast<const uint32_t*>(pl);
    al[1] = *reinterpret_cast<const uint32_t*>(pl + 8 * SROW);
    al[2] = *reinterpret_cast<const uint32_t*>(pl + 8);
    al[3] = *reinterpret_cast<const uint32_t*>(pl + 8 * SROW + 8);
#pragma unroll
    for (int nt = 0; nt < 8; nt++) {
      const __nv_bfloat16* pb  = &Wh[(cb + nt * 8 + rq) * SROW + kk + kq];
      const __nv_bfloat16* pbl = &Wl[(cb + nt * 8 + rq) * SROW + kk + kq];
      uint32_t bh0 = *reinterpret_cast<const uint32_t*>(pb);
      uint32_t bh1 = *reinterpret_cast<const uint32_t*>(pb + 8);
      uint32_t bl0 = *reinterpret_cast<const uint32_t*>(pbl);
      uint32_t bl1 = *reinterpret_cast<const uint32_t*>(pbl + 8);
      mma_bf16(acc[nt], ah, bh0, bh1);  // hi*hi
      mma_bf16(acc[nt], al, bh0, bh1);  // lo*hi
      mma_bf16(acc[nt], ah, bl0, bl1);  // hi*lo
    }
  }

  // epilogue: store + deterministic per-block BN partial stats
  int r = row0 + rb + rq;
  bool v0ok = r < KNT, v1ok = (r + 8) < KNT;
#pragma unroll
  for (int nt = 0; nt < 8; nt++) {
    int col = cb + nt * 8 + kq;
    float b0 = biasS[col], b1v = biasS[col + 1];
    float y00 = acc[nt][0] + b0, y01 = acc[nt][1] + b1v;
    float y10 = acc[nt][2] + b0, y11 = acc[nt][3] + b1v;
    if (v0ok) *reinterpret_cast<float2*>(out + (size_t)r * 128 + col) = make_float2(y00, y01);
    if (v1ok) *reinterpret_cast<float2*>(out + (size_t)(r + 8) * 128 + col) = make_float2(y10, y11);
    float s0 = (v0ok ? y00 : 0.f) + (v1ok ? y10 : 0.f);
    float s1 = (v0ok ? y01 : 0.f) + (v1ok ? y11 : 0.f);
    float q0 = (v0ok ? y00 * y00 : 0.f) + (v1ok ? y10 * y10 : 0.f);
    float q1 = (v0ok ? y01 * y01 : 0.f) + (v1ok ? y11 * y11 : 0.f);
#pragma unroll
    for (int o = 16; o >= 4; o >>= 1) {
      s0 += __shfl_xor_sync(0xffffffffu, s0, o);
      s1 += __shfl_xor_sync(0xffffffffu, s1, o);
      q0 += __shfl_xor_sync(0xffffffffu, q0, o);
      q1 += __shfl_xor_sync(0xffffffffu, q1, o);
    }
    if (rq == 0) {
      int wp = w >> 1;
      ssum[wp * 128 + col] = s0;
      ssum[wp * 128 + col + 1] = s1;
      ssq[wp * 128 + col] = q0;
      ssq[wp * 128 + col + 1] = q1;
    }
  }
  __syncthreads();
  if (t < 128) {
    float s = ssum[t] + ssum[128 + t] + ssum[256 + t] + ssum[384 + t];
    float q = ssq[t] + ssq[128 + t] + ssq[256 + t] + ssq[384 + t];
    g_psum[blockIdx.x * 128 + t] = s;
    g_psq[blockIdx.x * 128 + t] = q;
  }
}

// ---------------- reduce partials + BN params (deterministic fixed order) ----------
__global__ void redparams_kernel(const float* __restrict__ gamma,
                                 const float* __restrict__ beta, int which) {
  __shared__ float ssum[8 * 128], ssq[8 * 128];
  int t = threadIdx.x;  // 1024
  int col = t & 127, sl = t >> 7;
  int b0 = sl * 98, b1 = b0 + 98;
  if (b1 > NBLK_G) b1 = NBLK_G;
  float s = 0.f, q = 0.f;
  for (int b = b0; b < b1; b++) {
    s += g_psum[b * 128 + col];
    q += g_psq[b * 128 + col];
  }
  ssum[sl * 128 + col] = s;
  ssq[sl * 128 + col] = q;
  __syncthreads();
  if (t < 128) {
    float S = 0.f, Q = 0.f;
#pragma unroll
    for (int j = 0; j < 8; j++) {
      S += ssum[j * 128 + t];
      Q += ssq[j * 128 + t];
    }
    float inv = 1.0f / (float)KNT;
    float mu = S * inv;
    float var = Q * inv - mu * mu;
    float r = rsqrtf(var + BN_EPS);
    float sc = gamma[t] * r;
    g_scale[which * 128 + t] = sc;
    g_shift[which * 128 + t] = beta[t] - mu * sc;
  }
}

__global__ void finalize_kernel(float* __restrict__ out) {
  int i = blockIdx.x * blockDim.x + threadIdx.x;
  if (i >= KNT * 32) return;
  int c = (i & 31) << 2;
  float4 v = reinterpret_cast<float4*>(out)[i];
  v.x = fmaxf(fmaf(g_scale[128 + c + 0], v.x, g_shift[128 + c + 0]), 0.f);
  v.y = fmaxf(fmaf(g_scale[128 + c + 1], v.y, g_shift[128 + c + 1]), 0.f);
  v.z = fmaxf(fmaf(g_scale[128 + c + 2], v.z, g_shift[128 + c + 2]), 0.f);
  v.w = fmaxf(fmaf(g_scale[128 + c + 3], v.w, g_shift[128 + c + 3]), 0.f);
  reinterpret_cast<float4*>(out)[i] = v;
}

// ---------------- launch ----------------
extern "C" void kernel_launch(void* const* d_in, const int* in_sizes, int n_in,
                              void* d_out, int out_size) {
  const float* x_s = (const float*)d_in[0];
  const float* x_t = (const float*)d_in[1];
  const int* src = (const int*)d_in[2];  // int32 (JAX x64 disabled)
  const int* dst = (const int*)d_in[3];
  const float* eps = (const float*)d_in[4];
  const float* W1 = (const float*)d_in[5];
  const float* b1 = (const float*)d_in[6];
  const float* g1 = (const float*)d_in[7];
  const float* be1 = (const float*)d_in[8];
  const float* W2 = (const float*)d_in[9];
  const float* b2 = (const float*)d_in[10];
  const float* g2 = (const float*)d_in[11];
  const float* be2 = (const float*)d_in[12];
  float* out = (float*)d_out;

  const int SMEM = (64 * SROW + 128 * SROW) * 2 * 2 + (128 + 1024) * 4;  // 109056 B
  cudaFuncSetAttribute(gemm_kernel<1>, cudaFuncAttributeMaxDynamicSharedMemorySize, SMEM);
  cudaFuncSetAttribute(gemm_kernel<2>, cudaFuncAttributeMaxDynamicSharedMemorySize, SMEM);

  splitw_kernel<<<32, 256>>>(W1, W2);                       // #1 (also resets g_bar)
  build_kernel<<<NBLK_B, 512>>>(dst);                       // #2 zero+hist+scan
  scatter_kernel<<<(KE / 4 + 255) / 256, 256>>>(src, dst);  // #3
  gemm_kernel<1><<<NBLK_G, 256, SMEM>>>(x_s, x_t, eps, b1, nullptr);  // #4 (profiled)
  redparams_kernel<<<1, 1024>>>(g1, be1, 0);                // #5
  gemm_kernel<2><<<NBLK_G, 256, SMEM>>>(nullptr, nullptr, nullptr, b2, out);  // #6
  redparams_kernel<<<1, 1024>>>(g2, be2, 1);                // #7
  finalize_kernel<<<(KNT * 32 + 255) / 256, 256>>>(out);    // #8
}

// round 5
// speedup vs baseline: 1.1925x; 1.1925x over previous
#include <cuda_runtime.h>
#include <cuda_bf16.h>
#include <stdint.h>

#define KNS 100000
#define KNT 50000
#define KE  600000
#define KD  128
#define BN_EPS 1e-5f
#define NBLK_G 782     // ceil(KNT/64)
#define NBLK_B 98      // builder blocks (resident)

// ---------------- scratch (static device memory; no allocations) ----------------
__device__ float g_h[KNT * KD];
__device__ float g_y1[KNT * KD];
__device__ int   g_counts[KNT];
__device__ int   g_offsets[KNT + 1];
__device__ int   g_cursor[KNT];
__device__ int   g_srcs[KE];
__device__ float g_psum[NBLK_G * KD];
__device__ float g_psq[NBLK_G * KD];
__device__ float g_scale[2 * KD];
__device__ float g_shift[2 * KD];
__device__ int   g_bsum[128];
__device__ unsigned g_bar;
__device__ __align__(16) __nv_bfloat16 g_Wh[2 * KD * KD];
__device__ __align__(16) __nv_bfloat16 g_Wl[2 * KD * KD];

// ---------------- device-wide barrier (all NBLK_B blocks resident) ----------------
__device__ __forceinline__ void gridbar(unsigned target) {
  __syncthreads();
  if (threadIdx.x == 0) {
    __threadfence();
    atomicAdd(&g_bar, 1u);
    while (*((volatile unsigned*)&g_bar) < target) {}
  }
  __syncthreads();
}

// ---------------- precompute hi/lo bf16 split of weights; reset barrier ----------
__global__ void splitw_kernel(const float* __restrict__ W1,
                              const float* __restrict__ W2) {
  int i = blockIdx.x * 256 + threadIdx.x;  // 0..8191, 4 elems each
  if (i == 0) g_bar = 0;
  if (i >= 8192) return;
  const float* W = (i < 4096) ? W1 : W2;
  int local = (i < 4096) ? i : (i - 4096);
  float4 v = *reinterpret_cast<const float4*>(W + local * 4);
  float arr[4] = {v.x, v.y, v.z, v.w};
  int o = i * 4;
#pragma unroll
  for (int j = 0; j < 4; j++) {
    __nv_bfloat16 h = __float2bfloat16_rn(arr[j]);
    g_Wh[o + j] = h;
    g_Wl[o + j] = __float2bfloat16_rn(arr[j] - __bfloat162float(h));
  }
}

__device__ __forceinline__ int warp_incl_scan(int x, int lane) {
#pragma unroll
  for (int o = 1; o < 32; o <<= 1) {
    int y = __shfl_up_sync(0xffffffffu, x, o);
    if (lane >= o) x += y;
  }
  return x;
}

// ---------------- builder: zero + histogram + exclusive scan in ONE kernel --------
__global__ void build_kernel(const int* __restrict__ dst) {
  __shared__ int ws[16];
  __shared__ int sbase;
  int t = threadIdx.x, b = blockIdx.x;
  int i = b * 512 + t;
  int lane = t & 31, w = t >> 5;

  if (i < KNT) g_counts[i] = 0;
  gridbar(NBLK_B);

  const int4* dst4 = reinterpret_cast<const int4*>(dst);
  for (int e = i; e < KE / 4; e += NBLK_B * 512) {
    int4 d = dst4[e];
    atomicAdd(&g_counts[d.x], 1);
    atomicAdd(&g_counts[d.y], 1);
    atomicAdd(&g_counts[d.z], 1);
    atomicAdd(&g_counts[d.w], 1);
  }
  gridbar(2 * NBLK_B);

  int v = (i < KNT) ? __ldcg(&g_counts[i]) : 0;
  int x = warp_incl_scan(v, lane);
  if (lane == 31) ws[w] = x;
  __syncthreads();
  if (t < 16) {
    int y = ws[t];
#pragma unroll
    for (int o = 1; o < 16; o <<= 1) {
      int z = __shfl_up_sync(0xffffu, y, o);
      if (t >= o) y += z;
    }
    ws[t] = y;
  }
  __syncthreads();
  int incl = x + (w > 0 ? ws[w - 1] : 0);
  int ex = incl - v;
  if (t == 511) g_bsum[b] = incl;
  gridbar(3 * NBLK_B);

  int contrib = (t < b) ? __ldcg(&g_bsum[t]) : 0;
#pragma unroll
  for (int o = 16; o; o >>= 1) contrib += __shfl_down_sync(0xffffffffu, contrib, o);
  if (lane == 0) ws[w] = contrib;
  __syncthreads();
  if (t == 0) {
    int s = 0;
#pragma unroll
    for (int j = 0; j < 16; j++) s += ws[j];
    sbase = s;
  }
  __syncthreads();
  int off = ex + sbase;
  if (i < KNT) {
    g_offsets[i] = off;
    g_cursor[i] = off;
  }
  if (b == 0 && t == 0) g_offsets[KNT] = KE;
}

// ---------------- scatter src ids into CSR order (vectorized) ----------------------
__global__ void scatter_kernel(const int* __restrict__ src,
                               const int* __restrict__ dst) {
  int i = blockIdx.x * blockDim.x + threadIdx.x;
  if (i >= KE / 4) return;
  int4 s = reinterpret_cast<const int4*>(src)[i];
  int4 d = reinterpret_cast<const int4*>(dst)[i];
  g_srcs[atomicAdd(&g_cursor[d.x], 1)] = s.x;
  g_srcs[atomicAdd(&g_cursor[d.y], 1)] = s.y;
  g_srcs[atomicAdd(&g_cursor[d.z], 1)] = s.z;
  g_srcs[atomicAdd(&g_cursor[d.w], 1)] = s.w;
}

// ---------------- aggregation: one warp per target, high occupancy ----------------
__global__ void aggregate_kernel(const float* __restrict__ xs,
                                 const float* __restrict__ xt,
                                 const float* __restrict__ eps) {
  int gw = (blockIdx.x * blockDim.x + threadIdx.x) >> 5;
  int lane = threadIdx.x & 31;
  if (gw >= KNT) return;
  float sc = 1.0f + eps[0];
  const float4* xs4 = reinterpret_cast<const float4*>(xs);
  float4 a = reinterpret_cast<const float4*>(xt)[(size_t)gw * 32 + lane];
  a.x *= sc; a.y *= sc; a.z *= sc; a.w *= sc;
  float4 a1 = make_float4(0.f, 0.f, 0.f, 0.f);
  float4 a2 = make_float4(0.f, 0.f, 0.f, 0.f);
  float4 a3 = make_float4(0.f, 0.f, 0.f, 0.f);
  int beg = g_offsets[gw], end = g_offsets[gw + 1];
  int i = beg;
  for (; i + 3 < end; i += 4) {
    int s0 = g_srcs[i], s1 = g_srcs[i + 1], s2 = g_srcs[i + 2], s3 = g_srcs[i + 3];
    float4 v0 = xs4[(size_t)s0 * 32 + lane];
    float4 v1 = xs4[(size_t)s1 * 32 + lane];
    float4 v2 = xs4[(size_t)s2 * 32 + lane];
    float4 v3 = xs4[(size_t)s3 * 32 + lane];
    a.x += v0.x;  a.y += v0.y;  a.z += v0.z;  a.w += v0.w;
    a1.x += v1.x; a1.y += v1.y; a1.z += v1.z; a1.w += v1.w;
    a2.x += v2.x; a2.y += v2.y; a2.z += v2.z; a2.w += v2.w;
    a3.x += v3.x; a3.y += v3.y; a3.z += v3.z; a3.w += v3.w;
  }
  for (; i < end; i++) {
    float4 v0 = xs4[(size_t)g_srcs[i] * 32 + lane];
    a.x += v0.x; a.y += v0.y; a.z += v0.z; a.w += v0.w;
  }
  a.x += a1.x + a2.x + a3.x;
  a.y += a1.y + a2.y + a3.y;
  a.z += a1.z + a2.z + a3.z;
  a.w += a1.w + a2.w + a3.w;
  reinterpret_cast<float4*>(g_h)[(size_t)gw * 32 + lane] = a;
}

// ---------------- GEMM: ldmatrix B, A-from-global, bf16 hi/lo split ----------------
__device__ __forceinline__ void mma_bf16(float* c, const uint32_t* a,
                                         uint32_t b0, uint32_t b1) {
  asm volatile(
      "mma.sync.aligned.m16n8k16.row.col.f32.bf16.bf16.f32 "
      "{%0,%1,%2,%3}, {%4,%5,%6,%7}, {%8,%9}, {%0,%1,%2,%3};\n"
      : "+f"(c[0]), "+f"(c[1]), "+f"(c[2]), "+f"(c[3])
      : "r"(a[0]), "r"(a[1]), "r"(a[2]), "r"(a[3]), "r"(b0), "r"(b1));
}

__device__ __forceinline__ void ldsm4(uint32_t& r0, uint32_t& r1, uint32_t& r2,
                                      uint32_t& r3, uint32_t addr) {
  asm volatile("ldmatrix.sync.aligned.m8n8.x4.shared.b16 {%0,%1,%2,%3}, [%4];"
               : "=r"(r0), "=r"(r1), "=r"(r2), "=r"(r3) : "r"(addr));
}

__device__ __forceinline__ void split2(float x0, float x1, uint32_t& hi, uint32_t& lo) {
  __nv_bfloat162 H = __floats2bfloat162_rn(x0, x1);
  float l0 = x0 - __bfloat162float(H.x);
  float l1 = x1 - __bfloat162float(H.y);
  __nv_bfloat162 L = __floats2bfloat162_rn(l0, l1);
  hi = *reinterpret_cast<uint32_t*>(&H);
  lo = *reinterpret_cast<uint32_t*>(&L);
}

// smem: Wh[128 rows][256B] swizzled, Wl same (+32KB), then scale/shift/bias + stats
#define WSM_BYTES 32768
template <int LAYER>
__global__ __launch_bounds__(256, 2) void gemm_kernel(const float* __restrict__ bias,
                                                      float* __restrict__ out_param) {
  extern __shared__ char sm[];
  char* WhS = sm;
  char* WlS = sm + WSM_BYTES;
  float* scaleS = reinterpret_cast<float*>(sm + 2 * WSM_BYTES);  // 128
  float* shiftS = scaleS + 128;                                   // 128
  float* biasS = shiftS + 128;                                    // 128
  float* ssum = biasS + 128;                                      // 512
  float* ssq = ssum + 512;                                        // 512

  const float* A = (LAYER == 1) ? g_h : g_y1;
  float* out = (LAYER == 1) ? g_y1 : out_param;
  const __nv_bfloat16* GWh = g_Wh + (LAYER - 1) * KD * KD;
  const __nv_bfloat16* GWl = g_Wl + (LAYER - 1) * KD * KD;

  int t = threadIdx.x;
  int row0 = blockIdx.x * 64;
  int w = t >> 5, lane = t & 31;

  if (t < 128) {
    biasS[t] = bias[t];
    if (LAYER == 2) {
      scaleS[t] = g_scale[t];
      shiftS[t] = g_shift[t];
    }
  }
  // stage W hi/lo into swizzled smem: row r, 16B chunk c -> chunk c^(r&7)
  for (int idx = t; idx < 2048; idx += 256) {
    int r = idx >> 4, c = idx & 15;
    int db = r * 256 + ((c ^ (r & 7)) << 4);
    *reinterpret_cast<uint4*>(WhS + db) = reinterpret_cast<const uint4*>(GWh)[idx];
    *reinterpret_cast<uint4*>(WlS + db) = reinterpret_cast<const uint4*>(GWl)[idx];
  }
  __syncthreads();

  int rq = lane >> 2;          // 0..7
  int kq2 = (lane & 3) << 1;   // 0,2,4,6
  int rb = (w >> 1) * 16;
  int cb = (w & 1) * 64;

  // ldmatrix lane geometry for B tiles
  int n_lane = (lane & 7) + ((lane >> 4) << 3);  // 0..15
  int chunk_off = (lane >> 3) & 1;
  int swz7 = n_lane & 7;
  uint32_t whbase = (uint32_t)__cvta_generic_to_shared(WhS);
  uint32_t rowb[4];
#pragma unroll
  for (int p = 0; p < 4; p++) rowb[p] = whbase + (cb + p * 16 + n_lane) * 256;

  // A row pointers (clamped; invalid rows zeroed after load)
  int rA = row0 + rb + rq;
  bool v0ok = rA < KNT, v1ok = (rA + 8) < KNT;
  const float* base0 = A + (size_t)(v0ok ? rA : 0) * 128 + kq2;
  const float* base1 = A + (size_t)(v1ok ? rA + 8 : 0) * 128 + kq2;

  float acc[8][4];
#pragma unroll
  for (int i = 0; i < 8; i++)
#pragma unroll
    for (int j = 0; j < 4; j++) acc[i][j] = 0.f;

#pragma unroll
  for (int kk = 0; kk < 128; kk += 16) {
    // ---- A fragments straight from global (fp32 -> bf16 hi/lo) ----
    float2 f0 = *reinterpret_cast<const float2*>(base0 + kk);
    float2 f1 = *reinterpret_cast<const float2*>(base1 + kk);
    float2 f2 = *reinterpret_cast<const float2*>(base0 + kk + 8);
    float2 f3 = *reinterpret_cast<const float2*>(base1 + kk + 8);
    if (LAYER == 2) {
      float2 sA = *reinterpret_cast<const float2*>(&scaleS[kk + kq2]);
      float2 hA = *reinterpret_cast<const float2*>(&shiftS[kk + kq2]);
      float2 sB = *reinterpret_cast<const float2*>(&scaleS[kk + kq2 + 8]);
      float2 hB = *reinterpret_cast<const float2*>(&shiftS[kk + kq2 + 8]);
      f0.x = fmaxf(fmaf(sA.x, f0.x, hA.x), 0.f);
      f0.y = fmaxf(fmaf(sA.y, f0.y, hA.y), 0.f);
      f1.x = fmaxf(fmaf(sA.x, f1.x, hA.x), 0.f);
      f1.y = fmaxf(fmaf(sA.y, f1.y, hA.y), 0.f);
      f2.x = fmaxf(fmaf(sB.x, f2.x, hB.x), 0.f);
      f2.y = fmaxf(fmaf(sB.y, f2.y, hB.y), 0.f);
      f3.x = fmaxf(fmaf(sB.x, f3.x, hB.x), 0.f);
      f3.y = fmaxf(fmaf(sB.y, f3.y, hB.y), 0.f);
    }
    if (!v0ok) { f0.x = f0.y = f2.x = f2.y = 0.f; }
    if (!v1ok) { f1.x = f1.y = f3.x = f3.y = 0.f; }
    uint32_t ah[4], al[4];
    split2(f0.x, f0.y, ah[0], al[0]);
    split2(f1.x, f1.y, ah[1], al[1]);
    split2(f2.x, f2.y, ah[2], al[2]);
    split2(f3.x, f3.y, ah[3], al[3]);

    // ---- B via ldmatrix.x4 from swizzled smem ----
    int chunk = (kk >> 3) + chunk_off;
#pragma unroll
    for (int p = 0; p < 4; p++) {
      uint32_t addr = rowb[p] + ((chunk ^ swz7) << 4);
      uint32_t bh0, bh1, bh2, bh3, bl0, bl1, bl2, bl3;
      ldsm4(bh0, bh1, bh2, bh3, addr);
      ldsm4(bl0, bl1, bl2, bl3, addr + WSM_BYTES);
      mma_bf16(acc[2 * p], ah, bh0, bh1);
      mma_bf16(acc[2 * p], al, bh0, bh1);
      mma_bf16(acc[2 * p], ah, bl0, bl1);
      mma_bf16(acc[2 * p + 1], ah, bh2, bh3);
      mma_bf16(acc[2 * p + 1], al, bh2, bh3);
      mma_bf16(acc[2 * p + 1], ah, bl2, bl3);
    }
  }

  // epilogue: store + deterministic per-block BN partial stats
#pragma unroll
  for (int nt = 0; nt < 8; nt++) {
    int col = cb + nt * 8 + kq2;
    float b0 = biasS[col], b1v = biasS[col + 1];
    float y00 = acc[nt][0] + b0, y01 = acc[nt][1] + b1v;
    float y10 = acc[nt][2] + b0, y11 = acc[nt][3] + b1v;
    if (v0ok) *reinterpret_cast<float2*>(out + (size_t)rA * 128 + col) = make_float2(y00, y01);
    if (v1ok) *reinterpret_cast<float2*>(out + (size_t)(rA + 8) * 128 + col) = make_float2(y10, y11);
    float s0 = (v0ok ? y00 : 0.f) + (v1ok ? y10 : 0.f);
    float s1 = (v0ok ? y01 : 0.f) + (v1ok ? y11 : 0.f);
    float q0 = (v0ok ? y00 * y00 : 0.f) + (v1ok ? y10 * y10 : 0.f);
    float q1 = (v0ok ? y01 * y01 : 0.f) + (v1ok ? y11 * y11 : 0.f);
#pragma unroll
    for (int o = 16; o >= 4; o >>= 1) {
      s0 += __shfl_xor_sync(0xffffffffu, s0, o);
      s1 += __shfl_xor_sync(0xffffffffu, s1, o);
      q0 += __shfl_xor_sync(0xffffffffu, q0, o);
      q1 += __shfl_xor_sync(0xffffffffu, q1, o);
    }
    if (rq == 0) {
      int wp = w >> 1;
      ssum[wp * 128 + col] = s0;
      ssum[wp * 128 + col + 1] = s1;
      ssq[wp * 128 + col] = q0;
      ssq[wp * 128 + col + 1] = q1;
    }
  }
  __syncthreads();
  if (t < 128) {
    float s = ssum[t] + ssum[128 + t] + ssum[256 + t] + ssum[384 + t];
    float q = ssq[t] + ssq[128 + t] + ssq[256 + t] + ssq[384 + t];
    g_psum[blockIdx.x * 128 + t] = s;
    g_psq[blockIdx.x * 128 + t] = q;
  }
}

// ---------------- reduce partials + BN params (deterministic fixed order) ----------
__global__ void redparams_kernel(const float* __restrict__ gamma,
                                 const float* __restrict__ beta, int which) {
  __shared__ float ssum[8 * 128], ssq[8 * 128];
  int t = threadIdx.x;  // 1024
  int col = t & 127, sl = t >> 7;
  int b0 = sl * 98, b1 = b0 + 98;
  if (b1 > NBLK_G) b1 = NBLK_G;
  float s = 0.f, q = 0.f;
  for (int b = b0; b < b1; b++) {
    s += g_psum[b * 128 + col];
    q += g_psq[b * 128 + col];
  }
  ssum[sl * 128 + col] = s;
  ssq[sl * 128 + col] = q;
  __syncthreads();
  if (t < 128) {
    float S = 0.f, Q = 0.f;
#pragma unroll
    for (int j = 0; j < 8; j++) {
      S += ssum[j * 128 + t];
      Q += ssq[j * 128 + t];
    }
    float inv = 1.0f / (float)KNT;
    float mu = S * inv;
    float var = Q * inv - mu * mu;
    float r = rsqrtf(var + BN_EPS);
    float sc = gamma[t] * r;
    g_scale[which * 128 + t] = sc;
    g_shift[which * 128 + t] = beta[t] - mu * sc;
  }
}

__global__ void finalize_kernel(float* __restrict__ out) {
  int i = blockIdx.x * blockDim.x + threadIdx.x;
  if (i >= KNT * 32) return;
  int c = (i & 31) << 2;
  float4 v = reinterpret_cast<float4*>(out)[i];
  v.x = fmaxf(fmaf(g_scale[128 + c + 0], v.x, g_shift[128 + c + 0]), 0.f);
  v.y = fmaxf(fmaf(g_scale[128 + c + 1], v.y, g_shift[128 + c + 1]), 0.f);
  v.z = fmaxf(fmaf(g_scale[128 + c + 2], v.z, g_shift[128 + c + 2]), 0.f);
  v.w = fmaxf(fmaf(g_scale[128 + c + 3], v.w, g_shift[128 + c + 3]), 0.f);
  reinterpret_cast<float4*>(out)[i] = v;
}

// ---------------- launch ----------------
extern "C" void kernel_launch(void* const* d_in, const int* in_sizes, int n_in,
                              void* d_out, int out_size) {
  const float* x_s = (const float*)d_in[0];
  const float* x_t = (const float*)d_in[1];
  const int* src = (const int*)d_in[2];  // int32 (JAX x64 disabled)
  const int* dst = (const int*)d_in[3];
  const float* eps = (const float*)d_in[4];
  const float* W1 = (const float*)d_in[5];
  const float* b1 = (const float*)d_in[6];
  const float* g1 = (const float*)d_in[7];
  const float* be1 = (const float*)d_in[8];
  const float* W2 = (const float*)d_in[9];
  const float* b2 = (const float*)d_in[10];
  const float* g2 = (const float*)d_in[11];
  const float* be2 = (const float*)d_in[12];
  float* out = (float*)d_out;

  const int SMEM = 2 * WSM_BYTES + (128 * 3 + 1024) * 4;  // 71168 B
  cudaFuncSetAttribute(gemm_kernel<1>, cudaFuncAttributeMaxDynamicSharedMemorySize, SMEM);
  cudaFuncSetAttribute(gemm_kernel<2>, cudaFuncAttributeMaxDynamicSharedMemorySize, SMEM);

  splitw_kernel<<<32, 256>>>(W1, W2);                       // #1 (resets g_bar)
  build_kernel<<<NBLK_B, 512>>>(dst);                       // #2 zero+hist+scan
  scatter_kernel<<<(KE / 4 + 255) / 256, 256>>>(src, dst);  // #3
  aggregate_kernel<<<(KNT * 32 + 255) / 256, 256>>>(x_s, x_t, eps);  // #4
  gemm_kernel<1><<<NBLK_G, 256, SMEM>>>(b1, nullptr);       // #5
  redparams_kernel<<<1, 1024>>>(g1, be1, 0);                // #6 (profiled slot)
  gemm_kernel<2><<<NBLK_G, 256, SMEM>>>(b2, out);           // #7
  redparams_kernel<<<1, 1024>>>(g2, be2, 1);                // #8
  finalize_kernel<<<(KNT * 32 + 255) / 256, 256>>>(out);    // #9
}